// round 3
// baseline (speedup 1.0000x reference)
#include <cuda_runtime.h>
#include <math.h>

#define N_NODES 59392
#define HID     256
#define DOUT    232
#define DH      116
#define DEG     8
#define NPG     116
#define NGRAPH  512
#define QS      928   // q|k|v|s packed row stride

// ---------------- device scratch (no allocations allowed) ----------------
__device__ float g_W[HID * QS];                       // packed [256,928] weights
__device__ float g_qkvs[(size_t)N_NODES * QS];        // [N,928] q|k|v|s
__device__ float g_hproj[(size_t)N_NODES * DOUT];     // [N,232]
__device__ float g_e[N_NODES];                        // per-node mean
__device__ int   g_is64;                              // edge_index dtype flag

// ---------------- edge_index dtype probe ----------------
// JAX without x64 silently downgrades int64 -> int32. If the buffer really is
// int64 (little-endian), every odd 32-bit word is a zero hi-word. For int32
// data those slots are random src ids in graph 0 (uniform in [0,116)); the
// probability all five are zero is ~(1/116)^5.
__global__ void detect_dtype(const int* __restrict__ e32) {
    if (threadIdx.x == 0 && blockIdx.x == 0) {
        int z = (e32[1] == 0) & (e32[3] == 0) & (e32[5] == 0) &
                (e32[7] == 0) & (e32[9] == 0);
        g_is64 = z;
    }
}

// ---------------- pack Wq|Wk|Wv|Ws into [256,928] ----------------
__global__ void pack_w(const float* __restrict__ Wq, const float* __restrict__ Wk,
                       const float* __restrict__ Wv, const float* __restrict__ Ws) {
    int idx = blockIdx.x * blockDim.x + threadIdx.x;
    if (idx >= HID * DOUT) return;
    int k = idx / DOUT, n = idx % DOUT;
    float* row = g_W + (size_t)k * QS;
    row[n]       = Wq[idx];
    row[232 + n] = Wk[idx];
    row[464 + n] = Wv[idx];
    row[696 + n] = Ws[idx];
}

// ---------------- fp32 SGEMM: g_qkvs = A[59392,256] * g_W[256,928] ----------------
// 128x64 block tile, 16-deep K chunks, 8x4 per-thread microtile, 256 threads.
__global__ __launch_bounds__(256) void gemm_qkvs(const float* __restrict__ A) {
    __shared__ float As[16][128];
    __shared__ float Bs[16][64];
    const int tid = threadIdx.x;
    const int tx = tid & 15;       // 0..15 (N dim)
    const int ty = tid >> 4;       // 0..15 (M dim)
    const int row0 = blockIdx.y * 128;
    const int col0 = blockIdx.x * 64;

    float acc[8][4];
#pragma unroll
    for (int i = 0; i < 8; i++)
#pragma unroll
        for (int j = 0; j < 4; j++) acc[i][j] = 0.f;

    for (int k0 = 0; k0 < HID; k0 += 16) {
        // load A tile 128x16 (2 float4 per thread), store transposed
#pragma unroll
        for (int i = 0; i < 2; i++) {
            int lin = tid + i * 256;           // 0..511
            int r = lin >> 2;                  // row within tile
            int c = (lin & 3) * 4;             // k within chunk
            float4 v = *(const float4*)(A + (size_t)(row0 + r) * HID + k0 + c);
            As[c + 0][r] = v.x; As[c + 1][r] = v.y;
            As[c + 2][r] = v.z; As[c + 3][r] = v.w;
        }
        // load B tile 16x64 (1 float4 per thread)
        {
            int r = tid >> 4;                  // k within chunk
            int c = (tid & 15) * 4;            // n within tile
            int col = col0 + c;
            float4 v = make_float4(0.f, 0.f, 0.f, 0.f);
            if (col < QS) v = *(const float4*)(g_W + (size_t)(k0 + r) * QS + col);
            *(float4*)&Bs[r][c] = v;
        }
        __syncthreads();
#pragma unroll
        for (int kk = 0; kk < 16; kk++) {
            float a[8], b[4];
#pragma unroll
            for (int i = 0; i < 8; i++) a[i] = As[kk][ty * 8 + i];
#pragma unroll
            for (int j = 0; j < 4; j++) b[j] = Bs[kk][tx * 4 + j];
#pragma unroll
            for (int i = 0; i < 8; i++)
#pragma unroll
                for (int j = 0; j < 4; j++) acc[i][j] += a[i] * b[j];
        }
        __syncthreads();
    }
    // store
#pragma unroll
    for (int i = 0; i < 8; i++) {
        int r = row0 + ty * 8 + i;
        int c = col0 + tx * 4;
        if (c < QS) {
            float4 v = make_float4(acc[i][0], acc[i][1], acc[i][2], acc[i][3]);
            *(float4*)(g_qkvs + (size_t)r * QS + c) = v;
        }
    }
}

// ---------------- per-node edge attention (one warp per node) ----------------
__global__ __launch_bounds__(256) void attn_kernel(const int* __restrict__ e32) {
    const int warp = threadIdx.x >> 5;
    const int lane = threadIdx.x & 31;
    const int node = blockIdx.x * 8 + warp;
    if (node >= N_NODES) return;
    const int is64 = g_is64;

    const float* row = g_qkvs + (size_t)node * QS;
    float q[8];
#pragma unroll
    for (int j = 0; j < 8; j++) {
        int d = lane + 32 * j;
        q[j] = (d < DOUT) ? row[d] : 0.f;
    }
    int src[8];
#pragma unroll
    for (int e = 0; e < 8; e++) {
        int ei = node * 8 + e;
        src[e] = is64 ? e32[2 * ei] : e32[ei];
    }

    float s0[8], s1[8];
#pragma unroll
    for (int e = 0; e < 8; e++) {
        const float* kp = g_qkvs + (size_t)src[e] * QS + 232;
        float a0 = 0.f, a1 = 0.f;
#pragma unroll
        for (int j = 0; j < 8; j++) {
            int d = lane + 32 * j;
            if (d < DOUT) {
                float p = q[j] * kp[d];
                if (d < DH) a0 += p; else a1 += p;
            }
        }
#pragma unroll
        for (int o = 16; o > 0; o >>= 1) {
            a0 += __shfl_xor_sync(0xFFFFFFFFu, a0, o);
            a1 += __shfl_xor_sync(0xFFFFFFFFu, a1, o);
        }
        s0[e] = a0; s1[e] = a1;
    }

    const float scale = rsqrtf((float)DH);
    float m0 = -1e30f, m1 = -1e30f;
#pragma unroll
    for (int e = 0; e < 8; e++) {
        s0[e] *= scale; s1[e] *= scale;
        m0 = fmaxf(m0, s0[e]); m1 = fmaxf(m1, s1[e]);
    }
    float sum0 = 0.f, sum1 = 0.f;
    float a0w[8], a1w[8];
#pragma unroll
    for (int e = 0; e < 8; e++) {
        a0w[e] = expf(s0[e] - m0); sum0 += a0w[e];
        a1w[e] = expf(s1[e] - m1); sum1 += a1w[e];
    }
    float inv0 = 1.f / (sum0 + 1e-16f);
    float inv1 = 1.f / (sum1 + 1e-16f);
#pragma unroll
    for (int e = 0; e < 8; e++) { a0w[e] *= inv0; a1w[e] *= inv1; }

    // accumulate alpha * v[src] + skip (s = h@Ws at row+696)
    float acc[8];
#pragma unroll
    for (int j = 0; j < 8; j++) {
        int d = lane + 32 * j;
        acc[j] = (d < DOUT) ? row[696 + d] : 0.f;
    }
#pragma unroll
    for (int e = 0; e < 8; e++) {
        const float* vp = g_qkvs + (size_t)src[e] * QS + 464;
        float w0 = a0w[e], w1 = a1w[e];
#pragma unroll
        for (int j = 0; j < 8; j++) {
            int d = lane + 32 * j;
            if (d < DOUT) acc[j] += ((d < DH) ? w0 : w1) * vp[d];
        }
    }

    // mean over 232 + write h_proj
    float part = 0.f;
#pragma unroll
    for (int j = 0; j < 8; j++) part += acc[j];
#pragma unroll
    for (int o = 16; o > 0; o >>= 1) part += __shfl_xor_sync(0xFFFFFFFFu, part, o);

    float* hp = g_hproj + (size_t)node * DOUT;
#pragma unroll
    for (int j = 0; j < 8; j++) {
        int d = lane + 32 * j;
        if (d < DOUT) hp[d] = acc[j];
    }
    if (lane == 0) g_e[node] = part * (1.f / 232.f);
}

// ---------------- per-graph softmax + weighting ----------------
__global__ __launch_bounds__(128) void graph_softmax(float* __restrict__ out_alpha,
                                                     float* __restrict__ out_hw) {
    const int g = blockIdx.x;
    const int tid = threadIdx.x;
    __shared__ float sh[128];
    __shared__ float salpha[NPG];
    const int base = g * NPG;

    float v = (tid < NPG) ? g_e[base + tid] : -1e30f;
    sh[tid] = v; __syncthreads();
    for (int o = 64; o > 0; o >>= 1) {
        if (tid < o) sh[tid] = fmaxf(sh[tid], sh[tid + o]);
        __syncthreads();
    }
    float m = sh[0]; __syncthreads();
    float ex = (tid < NPG) ? expf(v - m) : 0.f;
    sh[tid] = ex; __syncthreads();
    for (int o = 64; o > 0; o >>= 1) {
        if (tid < o) sh[tid] += sh[tid + o];
        __syncthreads();
    }
    float s = sh[0];
    float alpha = ex / s;
    if (tid < NPG) {
        salpha[tid] = alpha;
        out_alpha[base + tid] = alpha;
    }
    __syncthreads();

    float* dst = out_hw + (size_t)base * DOUT;
    const float* src = g_hproj + (size_t)base * DOUT;
    for (int i = tid; i < NPG * DOUT; i += 128) {
        dst[i] = salpha[i / DOUT] * src[i];
    }
}

// ---------------- launch ----------------
extern "C" void kernel_launch(void* const* d_in, const int* in_sizes, int n_in,
                              void* d_out, int out_size) {
    const float* h    = (const float*)d_in[0];
    const int*   edge = (const int*)  d_in[1];   // row 0 = src
    // d_in[2] = batch_index (layout implied, unused)
    const float* Wq = (const float*)d_in[3];
    const float* Wk = (const float*)d_in[4];
    const float* Wv = (const float*)d_in[5];
    const float* Ws = (const float*)d_in[6];
    float* out = (float*)d_out;   // [0:59392) alpha_map, then h_weighted [N,232]

    detect_dtype<<<1, 32>>>(edge);
    pack_w<<<(HID * DOUT + 255) / 256, 256>>>(Wq, Wk, Wv, Ws);
    dim3 ggrid((QS + 63) / 64, N_NODES / 128);
    gemm_qkvs<<<ggrid, 256>>>(h);
    attn_kernel<<<N_NODES / 8, 256>>>(edge);
    graph_softmax<<<NGRAPH, 128>>>(out, out + N_NODES);
}

// round 7
// speedup vs baseline: 1.2439x; 1.2439x over previous
#include <cuda_runtime.h>
#include <math.h>
#include <stdint.h>

#define N_NODES 59392
#define HID     256
#define DOUT    232
#define DH      116
#define NPG     116
#define NGRAPH  512
#define NPAD    1024          // padded N for GEMM / qkvs row stride

// GEMM tiling
#define TM 128
#define TN 128
#define KC 32
// smem layout (floats); A tile 128 rows x 32 k, stride 36; B tile 32 k x 128 n, stride 136
#define ASTR 36
#define BSTR 136
#define A_TILE_F (TM * ASTR)              // 4608 floats = 18432 B
#define B_TILE_F (KC * BSTR)              // 4352 floats = 17408 B
#define SM_FLOATS (2 * (A_TILE_F + B_TILE_F))   // 17920 floats = 71680 B

// ---------------- device scratch (no allocations allowed) ----------------
__device__ float g_Wk[HID * NPAD];                    // [256,1024] packed q|k|v|s, tf32-rounded, zero pad
__device__ float g_qkvs[(size_t)N_NODES * NPAD];      // [N,1024] q|k|v|s (stride 1024)
__device__ float g_hproj[(size_t)N_NODES * DOUT];     // [N,232]
__device__ float g_e[N_NODES];                        // per-node mean
__device__ int   g_is64;                              // edge_index dtype flag

// ---------------- helpers ----------------
__device__ __forceinline__ uint32_t s2u(const void* p) {
    uint32_t a;
    asm("{ .reg .u64 t; cvta.to.shared.u64 t, %1; cvt.u32.u64 %0, t; }"
        : "=r"(a) : "l"(p));
    return a;
}
__device__ __forceinline__ uint32_t tf32r(float x) {
    uint32_t r;
    asm("cvt.rna.tf32.f32 %0, %1;" : "=r"(r) : "f"(x));
    return r;
}
__device__ __forceinline__ void cp16(uint32_t saddr, const void* gaddr) {
    asm volatile("cp.async.cg.shared.global [%0], [%1], 16;"
                 :: "r"(saddr), "l"(gaddr));
}
__device__ __forceinline__ void cp_commit() {
    asm volatile("cp.async.commit_group;" ::: "memory");
}
__device__ __forceinline__ void cp_wait0() {
    asm volatile("cp.async.wait_group 0;" ::: "memory");
}
__device__ __forceinline__ void mma_tf32(float& d0, float& d1, float& d2, float& d3,
                                         uint32_t a0, uint32_t a1, uint32_t a2, uint32_t a3,
                                         uint32_t b0, uint32_t b1) {
    asm volatile("mma.sync.aligned.m16n8k8.row.col.f32.tf32.tf32.f32 "
                 "{%0,%1,%2,%3}, {%4,%5,%6,%7}, {%8,%9}, {%0,%1,%2,%3};"
                 : "+f"(d0), "+f"(d1), "+f"(d2), "+f"(d3)
                 : "r"(a0), "r"(a1), "r"(a2), "r"(a3), "r"(b0), "r"(b1));
}

// ---------------- edge_index dtype probe ----------------
__global__ void detect_dtype(const int* __restrict__ e32) {
    if (threadIdx.x == 0 && blockIdx.x == 0) {
        int z = (e32[1] == 0) & (e32[3] == 0) & (e32[5] == 0) &
                (e32[7] == 0) & (e32[9] == 0);
        g_is64 = z;
    }
}

// ---------------- pack Wq|Wk|Wv|Ws into g_Wk[256,1024] (tf32-rounded) ----------------
__global__ void pack_w(const float* __restrict__ Wq, const float* __restrict__ Wk,
                       const float* __restrict__ Wv, const float* __restrict__ Ws) {
    int idx = blockIdx.x * blockDim.x + threadIdx.x;
    if (idx >= HID * DOUT) return;
    int k = idx / DOUT, n = idx % DOUT;
    float* row = g_Wk + (size_t)k * NPAD;
    row[n]       = __uint_as_float(tf32r(Wq[idx]));
    row[232 + n] = __uint_as_float(tf32r(Wk[idx]));
    row[464 + n] = __uint_as_float(tf32r(Wv[idx]));
    row[696 + n] = __uint_as_float(tf32r(Ws[idx]));
    // cols 928..1023 stay zero (static zero-init, never written)
}

// ---------------- tf32 mma.sync GEMM: g_qkvs = h[59392,256] @ Wk[256,1024] ----------------
// CTA 128x128, 8 warps (2 m x 4 n) of 64x32, K chunks of 32, cp.async double buffer.
__device__ __forceinline__ void load_chunk_g(float* As, float* Bs,
                                             const float* __restrict__ A,
                                             int row0, int col0, int k0, int tid) {
    uint32_t as = s2u(As), bs = s2u(Bs);
#pragma unroll
    for (int j = 0; j < 4; j++) {                 // A: 1024 float4
        int idx = tid + 256 * j;
        int m  = idx >> 3;
        int kq = (idx & 7) * 4;
        cp16(as + (m * ASTR + kq) * 4, A + (size_t)(row0 + m) * HID + k0 + kq);
    }
#pragma unroll
    for (int j = 0; j < 4; j++) {                 // B: 1024 float4
        int idx = tid + 256 * j;
        int kr = idx >> 5;
        int n  = (idx & 31) * 4;
        cp16(bs + (kr * BSTR + n) * 4, g_Wk + (size_t)(k0 + kr) * NPAD + col0 + n);
    }
    cp_commit();
}

__global__ __launch_bounds__(256) void gemm_mma(const float* __restrict__ A) {
    extern __shared__ float smem[];
    float* As[2] = { smem, smem + A_TILE_F + B_TILE_F };
    float* Bs[2] = { smem + A_TILE_F, smem + 2 * A_TILE_F + B_TILE_F };

    const int tid  = threadIdx.x;
    const int wid  = tid >> 5;
    const int lane = tid & 31;
    const int wm = (wid & 1) * 64;       // warp m offset
    const int wn = (wid >> 1) * 32;      // warp n offset
    const int r  = lane >> 2;            // 0..7
    const int c  = lane & 3;             // 0..3
    const int row0 = blockIdx.y * TM;
    const int col0 = blockIdx.x * TN;

    float d[4][4][4];
#pragma unroll
    for (int mi = 0; mi < 4; mi++)
#pragma unroll
        for (int ni = 0; ni < 4; ni++)
#pragma unroll
            for (int t = 0; t < 4; t++) d[mi][ni][t] = 0.f;

    load_chunk_g(As[0], Bs[0], A, row0, col0, 0, tid);

#pragma unroll 1
    for (int ch = 0; ch < HID / KC; ch++) {
        cp_wait0();
        __syncthreads();
        int buf = ch & 1;
        if (ch + 1 < HID / KC)
            load_chunk_g(As[buf ^ 1], Bs[buf ^ 1], A, row0, col0, (ch + 1) * KC, tid);

        const float* ap = As[buf] + (wm + r) * ASTR + c;
        const float* bp = Bs[buf] + c * BSTR + wn + r;
#pragma unroll
        for (int kk = 0; kk < KC; kk += 8) {
            uint32_t af[4][4], bf[4][2];
#pragma unroll
            for (int mi = 0; mi < 4; mi++) {
                const float* a = ap + mi * 16 * ASTR + kk;
                af[mi][0] = tf32r(a[0]);
                af[mi][1] = tf32r(a[8 * ASTR]);
                af[mi][2] = tf32r(a[4]);
                af[mi][3] = tf32r(a[8 * ASTR + 4]);
            }
#pragma unroll
            for (int ni = 0; ni < 4; ni++) {
                const float* b = bp + kk * BSTR + ni * 8;
                bf[ni][0] = __float_as_uint(b[0]);
                bf[ni][1] = __float_as_uint(b[4 * BSTR]);
            }
#pragma unroll
            for (int mi = 0; mi < 4; mi++)
#pragma unroll
                for (int ni = 0; ni < 4; ni++)
                    mma_tf32(d[mi][ni][0], d[mi][ni][1], d[mi][ni][2], d[mi][ni][3],
                             af[mi][0], af[mi][1], af[mi][2], af[mi][3],
                             bf[ni][0], bf[ni][1]);
        }
        __syncthreads();
    }

    // epilogue: direct stores (stride 1024, pad cols harmless)
    const int c2 = c * 2;
#pragma unroll
    for (int mi = 0; mi < 4; mi++) {
#pragma unroll
        for (int ni = 0; ni < 4; ni++) {
            int row = row0 + wm + mi * 16 + r;
            int col = col0 + wn + ni * 8 + c2;
            float2 lo = make_float2(d[mi][ni][0], d[mi][ni][1]);
            float2 hi = make_float2(d[mi][ni][2], d[mi][ni][3]);
            *(float2*)&g_qkvs[(size_t)row * NPAD + col] = lo;
            *(float2*)&g_qkvs[(size_t)(row + 8) * NPAD + col] = hi;
        }
    }
}

// ---------------- per-node edge attention (one warp per node) ----------------
__global__ __launch_bounds__(256) void attn_kernel(const int* __restrict__ e32) {
    const int warp = threadIdx.x >> 5;
    const int lane = threadIdx.x & 31;
    const int node = blockIdx.x * 8 + warp;
    if (node >= N_NODES) return;
    const int is64 = g_is64;

    const float* row = g_qkvs + (size_t)node * NPAD;
    float q[8];
#pragma unroll
    for (int j = 0; j < 8; j++) {
        int d = lane + 32 * j;
        q[j] = (d < DOUT) ? row[d] : 0.f;
    }
    int src[8];
#pragma unroll
    for (int e = 0; e < 8; e++) {
        int ei = node * 8 + e;
        src[e] = is64 ? e32[2 * ei] : e32[ei];
    }

    float s0[8], s1[8];
#pragma unroll
    for (int e = 0; e < 8; e++) {
        const float* kp = g_qkvs + (size_t)src[e] * NPAD + 232;
        float a0 = 0.f, a1 = 0.f;
#pragma unroll
        for (int j = 0; j < 8; j++) {
            int d = lane + 32 * j;
            if (d < DOUT) {
                float p = q[j] * kp[d];
                if (d < DH) a0 += p; else a1 += p;
            }
        }
#pragma unroll
        for (int o = 16; o > 0; o >>= 1) {
            a0 += __shfl_xor_sync(0xFFFFFFFFu, a0, o);
            a1 += __shfl_xor_sync(0xFFFFFFFFu, a1, o);
        }
        s0[e] = a0; s1[e] = a1;
    }

    const float scale = rsqrtf((float)DH);
    float m0 = -1e30f, m1 = -1e30f;
#pragma unroll
    for (int e = 0; e < 8; e++) {
        s0[e] *= scale; s1[e] *= scale;
        m0 = fmaxf(m0, s0[e]); m1 = fmaxf(m1, s1[e]);
    }
    float sum0 = 0.f, sum1 = 0.f;
    float a0w[8], a1w[8];
#pragma unroll
    for (int e = 0; e < 8; e++) {
        a0w[e] = expf(s0[e] - m0); sum0 += a0w[e];
        a1w[e] = expf(s1[e] - m1); sum1 += a1w[e];
    }
    float inv0 = 1.f / (sum0 + 1e-16f);
    float inv1 = 1.f / (sum1 + 1e-16f);
#pragma unroll
    for (int e = 0; e < 8; e++) { a0w[e] *= inv0; a1w[e] *= inv1; }

    float acc[8];
#pragma unroll
    for (int j = 0; j < 8; j++) {
        int d = lane + 32 * j;
        acc[j] = (d < DOUT) ? row[696 + d] : 0.f;
    }
#pragma unroll
    for (int e = 0; e < 8; e++) {
        const float* vp = g_qkvs + (size_t)src[e] * NPAD + 464;
        float w0 = a0w[e], w1 = a1w[e];
#pragma unroll
        for (int j = 0; j < 8; j++) {
            int d = lane + 32 * j;
            if (d < DOUT) acc[j] += ((d < DH) ? w0 : w1) * vp[d];
        }
    }

    float part = 0.f;
#pragma unroll
    for (int j = 0; j < 8; j++) part += acc[j];
#pragma unroll
    for (int o = 16; o > 0; o >>= 1) part += __shfl_xor_sync(0xFFFFFFFFu, part, o);

    float* hp = g_hproj + (size_t)node * DOUT;
#pragma unroll
    for (int j = 0; j < 8; j++) {
        int d = lane + 32 * j;
        if (d < DOUT) hp[d] = acc[j];
    }
    if (lane == 0) g_e[node] = part * (1.f / 232.f);
}

// ---------------- per-graph softmax + weighting ----------------
__global__ __launch_bounds__(128) void graph_softmax(float* __restrict__ out_alpha,
                                                     float* __restrict__ out_hw) {
    const int g = blockIdx.x;
    const int tid = threadIdx.x;
    __shared__ float sh[128];
    __shared__ float salpha[NPG];
    const int base = g * NPG;

    float v = (tid < NPG) ? g_e[base + tid] : -1e30f;
    sh[tid] = v; __syncthreads();
    for (int o = 64; o > 0; o >>= 1) {
        if (tid < o) sh[tid] = fmaxf(sh[tid], sh[tid + o]);
        __syncthreads();
    }
    float m = sh[0]; __syncthreads();
    float ex = (tid < NPG) ? expf(v - m) : 0.f;
    sh[tid] = ex; __syncthreads();
    for (int o = 64; o > 0; o >>= 1) {
        if (tid < o) sh[tid] += sh[tid + o];
        __syncthreads();
    }
    float s = sh[0];
    float alpha = ex / s;
    if (tid < NPG) {
        salpha[tid] = alpha;
        out_alpha[base + tid] = alpha;
    }
    __syncthreads();

    float* dst = out_hw + (size_t)base * DOUT;
    const float* src = g_hproj + (size_t)base * DOUT;
    for (int i = tid; i < NPG * DOUT; i += 128) {
        dst[i] = salpha[i / DOUT] * src[i];
    }
}

// ---------------- launch ----------------
extern "C" void kernel_launch(void* const* d_in, const int* in_sizes, int n_in,
                              void* d_out, int out_size) {
    const float* h    = (const float*)d_in[0];
    const int*   edge = (const int*)  d_in[1];   // row 0 = src
    const float* Wq = (const float*)d_in[3];
    const float* Wk = (const float*)d_in[4];
    const float* Wv = (const float*)d_in[5];
    const float* Ws = (const float*)d_in[6];
    float* out = (float*)d_out;   // [0:59392) alpha_map, then h_weighted [N,232]

    cudaFuncSetAttribute(gemm_mma, cudaFuncAttributeMaxDynamicSharedMemorySize,
                         SM_FLOATS * 4);

    detect_dtype<<<1, 32>>>(edge);
    pack_w<<<(HID * DOUT + 255) / 256, 256>>>(Wq, Wk, Wv, Ws);
    dim3 ggrid(NPAD / TN, N_NODES / TM);   // (8, 464)
    gemm_mma<<<ggrid, 256, SM_FLOATS * 4>>>(h);
    attn_kernel<<<N_NODES / 8, 256>>>(edge);
    graph_softmax<<<NGRAPH, 128>>>(out, out + N_NODES);
}

// round 8
// speedup vs baseline: 1.9991x; 1.6072x over previous
#include <cuda_runtime.h>
#include <cuda_fp16.h>
#include <math.h>
#include <stdint.h>

#define N_NODES 59392
#define HID     256
#define DOUT    232
#define DH      116
#define NPG     116
#define NGRAPH  512
#define QS      928           // qkvs row stride (output of GEMM)
#define NPAD    1024          // padded GEMM N

// GEMM tiling
#define TM 128
#define TN 128
#define KC 32
#define NCH (HID / KC)        // 8
// smem strides in halves (pad for conflict-free ldmatrix)
#define ASTR 40               // 32 + 8
#define BSTR 136              // 128 + 8
#define A_T (TM * ASTR)       // 5120 halves
#define B_T (KC * BSTR)       // 4352 halves
#define SM_HALVES (2 * (A_T + B_T))   // 18944 halves = 37888 B

// ---------------- device scratch (no allocations allowed) ----------------
__device__ __align__(16) __half g_hf16[(size_t)N_NODES * HID];   // h in fp16
__device__ __align__(16) __half g_Wh[HID * NPAD];                // [256,1024] q|k|v|s fp16, zero pad
__device__ __align__(16) float  g_qkvs[(size_t)N_NODES * QS];    // [N,928] q|k|v|s fp32
__device__ float g_hproj[(size_t)N_NODES * DOUT];                // [N,232]
__device__ float g_e[N_NODES];                                   // per-node mean
__device__ int   g_is64;                                         // edge_index dtype flag

// ---------------- helpers ----------------
__device__ __forceinline__ uint32_t s2u(const void* p) {
    uint32_t a;
    asm("{ .reg .u64 t; cvta.to.shared.u64 t, %1; cvt.u32.u64 %0, t; }"
        : "=r"(a) : "l"(p));
    return a;
}
__device__ __forceinline__ void cp16(uint32_t saddr, const void* gaddr) {
    asm volatile("cp.async.cg.shared.global [%0], [%1], 16;"
                 :: "r"(saddr), "l"(gaddr));
}
__device__ __forceinline__ void ldm4(uint32_t& r0, uint32_t& r1, uint32_t& r2,
                                     uint32_t& r3, uint32_t a) {
    asm volatile("ldmatrix.sync.aligned.m8n8.x4.shared.b16 {%0,%1,%2,%3}, [%4];"
                 : "=r"(r0), "=r"(r1), "=r"(r2), "=r"(r3) : "r"(a));
}
__device__ __forceinline__ void ldm4t(uint32_t& r0, uint32_t& r1, uint32_t& r2,
                                      uint32_t& r3, uint32_t a) {
    asm volatile("ldmatrix.sync.aligned.m8n8.x4.trans.shared.b16 {%0,%1,%2,%3}, [%4];"
                 : "=r"(r0), "=r"(r1), "=r"(r2), "=r"(r3) : "r"(a));
}
__device__ __forceinline__ void mma_f16(float& d0, float& d1, float& d2, float& d3,
                                        uint32_t a0, uint32_t a1, uint32_t a2, uint32_t a3,
                                        uint32_t b0, uint32_t b1) {
    asm volatile("mma.sync.aligned.m16n8k16.row.col.f32.f16.f16.f32 "
                 "{%0,%1,%2,%3}, {%4,%5,%6,%7}, {%8,%9}, {%0,%1,%2,%3};"
                 : "+f"(d0), "+f"(d1), "+f"(d2), "+f"(d3)
                 : "r"(a0), "r"(a1), "r"(a2), "r"(a3), "r"(b0), "r"(b1));
}

// ---------------- edge_index dtype probe ----------------
__global__ void detect_dtype(const int* __restrict__ e32) {
    if (threadIdx.x == 0 && blockIdx.x == 0) {
        int z = (e32[1] == 0) & (e32[3] == 0) & (e32[5] == 0) &
                (e32[7] == 0) & (e32[9] == 0);
        g_is64 = z;
    }
}

// ---------------- convert h -> fp16 ----------------
__global__ __launch_bounds__(256) void conv_h(const float* __restrict__ h) {
    size_t i = ((size_t)blockIdx.x * blockDim.x + threadIdx.x) * 4;
    if (i < (size_t)N_NODES * HID) {
        float4 v = *(const float4*)(h + i);
        __half2* dst = (__half2*)(g_hf16 + i);
        dst[0] = __floats2half2_rn(v.x, v.y);
        dst[1] = __floats2half2_rn(v.z, v.w);
    }
}

// ---------------- pack Wq|Wk|Wv|Ws into g_Wh[256,1024] fp16 ----------------
__global__ void pack_w(const float* __restrict__ Wq, const float* __restrict__ Wk,
                       const float* __restrict__ Wv, const float* __restrict__ Ws) {
    int idx = blockIdx.x * blockDim.x + threadIdx.x;
    if (idx >= HID * DOUT) return;
    int k = idx / DOUT, n = idx % DOUT;
    __half* row = g_Wh + (size_t)k * NPAD;
    row[n]       = __float2half_rn(Wq[idx]);
    row[232 + n] = __float2half_rn(Wk[idx]);
    row[464 + n] = __float2half_rn(Wv[idx]);
    row[696 + n] = __float2half_rn(Ws[idx]);
    // cols 928..1023 stay zero (static zero-init)
}

// ---------------- fp16 HGEMM: g_qkvs = h[59392,256] @ Wh[256,1024] ----------------
// CTA 128x128, 8 warps (2m x 4n) of 64x32, K chunks of 32, cp.async double buffer.
__device__ __forceinline__ void load_chunk(uint32_t as, uint32_t bs,
                                           int row0, int col0, int k0, int tid) {
#pragma unroll
    for (int j = 0; j < 2; j++) {                 // A: 512 cp16
        int idx = tid + 256 * j;
        int m  = idx >> 2;
        int kq = (idx & 3) * 8;
        cp16(as + (m * ASTR + kq) * 2,
             g_hf16 + (size_t)(row0 + m) * HID + k0 + kq);
    }
#pragma unroll
    for (int j = 0; j < 2; j++) {                 // B: 512 cp16
        int idx = tid + 256 * j;
        int kr = idx >> 4;
        int n  = (idx & 15) * 8;
        cp16(bs + (kr * BSTR + n) * 2,
             g_Wh + (size_t)(k0 + kr) * NPAD + col0 + n);
    }
    asm volatile("cp.async.commit_group;" ::: "memory");
}

__device__ __forceinline__ void compute_chunk(uint32_t as, uint32_t bs,
                                              int wm, int wn, int lane,
                                              float d[4][4][4]) {
    const int lrow = lane & 15;
    const int lsel = (lane >> 4) << 3;
#pragma unroll
    for (int kk = 0; kk < KC; kk += 16) {
        uint32_t af[4][4], bf[4][2];
#pragma unroll
        for (int mi = 0; mi < 4; mi++) {
            uint32_t a = as + ((wm + mi * 16 + lrow) * ASTR + kk + lsel) * 2;
            ldm4(af[mi][0], af[mi][1], af[mi][2], af[mi][3], a);
        }
#pragma unroll
        for (int nj = 0; nj < 2; nj++) {
            uint32_t a = bs + ((kk + lrow) * BSTR + wn + nj * 16 + lsel) * 2;
            uint32_t r0, r1, r2, r3;
            ldm4t(r0, r1, r2, r3, a);
            bf[nj * 2][0] = r0;     bf[nj * 2][1] = r1;
            bf[nj * 2 + 1][0] = r2; bf[nj * 2 + 1][1] = r3;
        }
#pragma unroll
        for (int mi = 0; mi < 4; mi++)
#pragma unroll
            for (int ni = 0; ni < 4; ni++)
                mma_f16(d[mi][ni][0], d[mi][ni][1], d[mi][ni][2], d[mi][ni][3],
                        af[mi][0], af[mi][1], af[mi][2], af[mi][3],
                        bf[ni][0], bf[ni][1]);
    }
}

__global__ __launch_bounds__(256) void gemm_hmma() {
    __shared__ __half smem[SM_HALVES];
    const uint32_t sbase = s2u(smem);
    const uint32_t asb[2] = { sbase, sbase + (A_T + B_T) * 2 };
    const uint32_t bsb[2] = { sbase + A_T * 2, sbase + (2 * A_T + B_T) * 2 };

    const int tid  = threadIdx.x;
    const int wid  = tid >> 5;
    const int lane = tid & 31;
    const int wm = (wid & 1) * 64;
    const int wn = (wid >> 1) * 32;
    const int r  = lane >> 2;
    const int c  = lane & 3;
    const int row0 = blockIdx.y * TM;
    const int col0 = blockIdx.x * TN;

    float d[4][4][4];
#pragma unroll
    for (int mi = 0; mi < 4; mi++)
#pragma unroll
        for (int ni = 0; ni < 4; ni++)
#pragma unroll
            for (int t = 0; t < 4; t++) d[mi][ni][t] = 0.f;

    load_chunk(asb[0], bsb[0], row0, col0, 0, tid);

#pragma unroll
    for (int ch = 0; ch < NCH; ch++) {
        if (ch + 1 < NCH)
            load_chunk(asb[(ch + 1) & 1], bsb[(ch + 1) & 1], row0, col0,
                       (ch + 1) * KC, tid);
        if (ch + 1 < NCH)
            asm volatile("cp.async.wait_group 1;" ::: "memory");
        else
            asm volatile("cp.async.wait_group 0;" ::: "memory");
        __syncthreads();
        compute_chunk(asb[ch & 1], bsb[ch & 1], wm, wn, lane, d);
        __syncthreads();
    }

    // epilogue: predicated stores into stride-928 qkvs
    const int c2 = c * 2;
#pragma unroll
    for (int mi = 0; mi < 4; mi++) {
#pragma unroll
        for (int ni = 0; ni < 4; ni++) {
            int row = row0 + wm + mi * 16 + r;
            int col = col0 + wn + ni * 8 + c2;
            if (col < QS) {
                *(float2*)&g_qkvs[(size_t)row * QS + col] =
                    make_float2(d[mi][ni][0], d[mi][ni][1]);
                *(float2*)&g_qkvs[(size_t)(row + 8) * QS + col] =
                    make_float2(d[mi][ni][2], d[mi][ni][3]);
            }
        }
    }
}

// ---------------- per-node edge attention (one warp per node) ----------------
__global__ __launch_bounds__(256) void attn_kernel(const int* __restrict__ e32) {
    const int warp = threadIdx.x >> 5;
    const int lane = threadIdx.x & 31;
    const int node = blockIdx.x * 8 + warp;
    if (node >= N_NODES) return;
    const int is64 = g_is64;

    const float* row = g_qkvs + (size_t)node * QS;
    float q[8];
#pragma unroll
    for (int j = 0; j < 8; j++) {
        int d = lane + 32 * j;
        q[j] = (d < DOUT) ? row[d] : 0.f;
    }
    int src[8];
#pragma unroll
    for (int e = 0; e < 8; e++) {
        int ei = node * 8 + e;
        src[e] = is64 ? e32[2 * ei] : e32[ei];
    }

    float s0[8], s1[8];
#pragma unroll
    for (int e = 0; e < 8; e++) {
        const float* kp = g_qkvs + (size_t)src[e] * QS + 232;
        float a0 = 0.f, a1 = 0.f;
#pragma unroll
        for (int j = 0; j < 8; j++) {
            int d = lane + 32 * j;
            if (d < DOUT) {
                float p = q[j] * kp[d];
                if (d < DH) a0 += p; else a1 += p;
            }
        }
#pragma unroll
        for (int o = 16; o > 0; o >>= 1) {
            a0 += __shfl_xor_sync(0xFFFFFFFFu, a0, o);
            a1 += __shfl_xor_sync(0xFFFFFFFFu, a1, o);
        }
        s0[e] = a0; s1[e] = a1;
    }

    const float scale = rsqrtf((float)DH);
    float m0 = -1e30f, m1 = -1e30f;
#pragma unroll
    for (int e = 0; e < 8; e++) {
        s0[e] *= scale; s1[e] *= scale;
        m0 = fmaxf(m0, s0[e]); m1 = fmaxf(m1, s1[e]);
    }
    float sum0 = 0.f, sum1 = 0.f;
    float a0w[8], a1w[8];
#pragma unroll
    for (int e = 0; e < 8; e++) {
        a0w[e] = expf(s0[e] - m0); sum0 += a0w[e];
        a1w[e] = expf(s1[e] - m1); sum1 += a1w[e];
    }
    float inv0 = 1.f / (sum0 + 1e-16f);
    float inv1 = 1.f / (sum1 + 1e-16f);
#pragma unroll
    for (int e = 0; e < 8; e++) { a0w[e] *= inv0; a1w[e] *= inv1; }

    float acc[8];
#pragma unroll
    for (int j = 0; j < 8; j++) {
        int d = lane + 32 * j;
        acc[j] = (d < DOUT) ? row[696 + d] : 0.f;
    }
#pragma unroll
    for (int e = 0; e < 8; e++) {
        const float* vp = g_qkvs + (size_t)src[e] * QS + 464;
        float w0 = a0w[e], w1 = a1w[e];
#pragma unroll
        for (int j = 0; j < 8; j++) {
            int d = lane + 32 * j;
            if (d < DOUT) acc[j] += ((d < DH) ? w0 : w1) * vp[d];
        }
    }

    float part = 0.f;
#pragma unroll
    for (int j = 0; j < 8; j++) part += acc[j];
#pragma unroll
    for (int o = 16; o > 0; o >>= 1) part += __shfl_xor_sync(0xFFFFFFFFu, part, o);

    float* hp = g_hproj + (size_t)node * DOUT;
#pragma unroll
    for (int j = 0; j < 8; j++) {
        int d = lane + 32 * j;
        if (d < DOUT) hp[d] = acc[j];
    }
    if (lane == 0) g_e[node] = part * (1.f / 232.f);
}

// ---------------- per-graph softmax + weighting ----------------
__global__ __launch_bounds__(128) void graph_softmax(float* __restrict__ out_alpha,
                                                     float* __restrict__ out_hw) {
    const int g = blockIdx.x;
    const int tid = threadIdx.x;
    __shared__ float sh[128];
    __shared__ float salpha[NPG];
    const int base = g * NPG;

    float v = (tid < NPG) ? g_e[base + tid] : -1e30f;
    sh[tid] = v; __syncthreads();
    for (int o = 64; o > 0; o >>= 1) {
        if (tid < o) sh[tid] = fmaxf(sh[tid], sh[tid + o]);
        __syncthreads();
    }
    float m = sh[0]; __syncthreads();
    float ex = (tid < NPG) ? expf(v - m) : 0.f;
    sh[tid] = ex; __syncthreads();
    for (int o = 64; o > 0; o >>= 1) {
        if (tid < o) sh[tid] += sh[tid + o];
        __syncthreads();
    }
    float s = sh[0];
    float alpha = ex / s;
    if (tid < NPG) {
        salpha[tid] = alpha;
        out_alpha[base + tid] = alpha;
    }
    __syncthreads();

    float* dst = out_hw + (size_t)base * DOUT;
    const float* src = g_hproj + (size_t)base * DOUT;
    for (int i = tid; i < NPG * DOUT; i += 128) {
        dst[i] = salpha[i / DOUT] * src[i];
    }
}

// ---------------- launch ----------------
extern "C" void kernel_launch(void* const* d_in, const int* in_sizes, int n_in,
                              void* d_out, int out_size) {
    const float* h    = (const float*)d_in[0];
    const int*   edge = (const int*)  d_in[1];   // row 0 = src
    const float* Wq = (const float*)d_in[3];
    const float* Wk = (const float*)d_in[4];
    const float* Wv = (const float*)d_in[5];
    const float* Ws = (const float*)d_in[6];
    float* out = (float*)d_out;   // [0:59392) alpha_map, then h_weighted [N,232]

    detect_dtype<<<1, 32>>>(edge);
    conv_h<<<(N_NODES * HID / 4 + 255) / 256, 256>>>(h);
    pack_w<<<(HID * DOUT + 255) / 256, 256>>>(Wq, Wk, Wv, Ws);
    dim3 ggrid(NPAD / TN, N_NODES / TM);   // (8, 464)
    gemm_hmma<<<ggrid, 256>>>();
    attn_kernel<<<N_NODES / 8, 256>>>(edge);
    graph_softmax<<<NGRAPH, 128>>>(out, out + N_NODES);
}

// round 9
// speedup vs baseline: 3.4000x; 1.7007x over previous
#include <cuda_runtime.h>
#include <cuda_fp16.h>
#include <math.h>
#include <stdint.h>

#define N_NODES 59392
#define HID     256
#define DOUT    232
#define DH      116
#define NPG     116
#define NGRAPH  512
#define QS      928           // qkvs row stride (floats)
#define NPAD    1024          // padded GEMM N

// GEMM tiling
#define TM 128
#define TN 128
#define KC 64
#define NCH (HID / KC)        // 4
// smem strides in halves (conflict-free for ldmatrix: stride/8 odd mod 8)
#define ASTR 72               // 64 + 8
#define BSTR 136              // 128 + 8
#define A_T (TM * ASTR)       // 9216 halves
#define B_T (KC * BSTR)       // 8704 halves
#define SM_BYTES (2 * (A_T + B_T) * 2)   // 71680 B

// ---------------- device scratch (no allocations allowed) ----------------
__device__ __align__(16) __half g_hf16[(size_t)N_NODES * HID];   // h in fp16
__device__ __align__(16) __half g_Wh[HID * NPAD];                // [256,1024] q|k|v|s fp16, zero pad
__device__ __align__(16) float  g_qkvs[(size_t)N_NODES * QS];    // [N,928] q|k|v|s fp32
__device__ __align__(16) float  g_hproj[(size_t)N_NODES * DOUT]; // [N,232]
__device__ float g_e[N_NODES];                                   // per-node mean
__device__ int   g_is64;                                         // edge_index dtype flag

// ---------------- helpers ----------------
__device__ __forceinline__ uint32_t s2u(const void* p) {
    uint32_t a;
    asm("{ .reg .u64 t; cvta.to.shared.u64 t, %1; cvt.u32.u64 %0, t; }"
        : "=r"(a) : "l"(p));
    return a;
}
__device__ __forceinline__ void cp16(uint32_t saddr, const void* gaddr) {
    asm volatile("cp.async.cg.shared.global [%0], [%1], 16;"
                 :: "r"(saddr), "l"(gaddr));
}
__device__ __forceinline__ void ldm4(uint32_t& r0, uint32_t& r1, uint32_t& r2,
                                     uint32_t& r3, uint32_t a) {
    asm volatile("ldmatrix.sync.aligned.m8n8.x4.shared.b16 {%0,%1,%2,%3}, [%4];"
                 : "=r"(r0), "=r"(r1), "=r"(r2), "=r"(r3) : "r"(a));
}
__device__ __forceinline__ void ldm4t(uint32_t& r0, uint32_t& r1, uint32_t& r2,
                                      uint32_t& r3, uint32_t a) {
    asm volatile("ldmatrix.sync.aligned.m8n8.x4.trans.shared.b16 {%0,%1,%2,%3}, [%4];"
                 : "=r"(r0), "=r"(r1), "=r"(r2), "=r"(r3) : "r"(a));
}
__device__ __forceinline__ void mma_f16(float& d0, float& d1, float& d2, float& d3,
                                        uint32_t a0, uint32_t a1, uint32_t a2, uint32_t a3,
                                        uint32_t b0, uint32_t b1) {
    asm volatile("mma.sync.aligned.m16n8k16.row.col.f32.f16.f16.f32 "
                 "{%0,%1,%2,%3}, {%4,%5,%6,%7}, {%8,%9}, {%0,%1,%2,%3};"
                 : "+f"(d0), "+f"(d1), "+f"(d2), "+f"(d3)
                 : "r"(a0), "r"(a1), "r"(a2), "r"(a3), "r"(b0), "r"(b1));
}
__device__ __forceinline__ float dot4(float4 a, float4 b) {
    return a.x * b.x + a.y * b.y + a.z * b.z + a.w * b.w;
}

// ---------------- edge_index dtype probe ----------------
__global__ void detect_dtype(const int* __restrict__ e32) {
    if (threadIdx.x == 0 && blockIdx.x == 0) {
        int z = (e32[1] == 0) & (e32[3] == 0) & (e32[5] == 0) &
                (e32[7] == 0) & (e32[9] == 0);
        g_is64 = z;
    }
}

// ---------------- convert h -> fp16 ----------------
__global__ __launch_bounds__(256) void conv_h(const float* __restrict__ h) {
    size_t i = ((size_t)blockIdx.x * blockDim.x + threadIdx.x) * 4;
    if (i < (size_t)N_NODES * HID) {
        float4 v = *(const float4*)(h + i);
        __half2* dst = (__half2*)(g_hf16 + i);
        dst[0] = __floats2half2_rn(v.x, v.y);
        dst[1] = __floats2half2_rn(v.z, v.w);
    }
}

// ---------------- pack Wq|Wk|Wv|Ws into g_Wh[256,1024] fp16 ----------------
__global__ void pack_w(const float* __restrict__ Wq, const float* __restrict__ Wk,
                       const float* __restrict__ Wv, const float* __restrict__ Ws) {
    int idx = blockIdx.x * blockDim.x + threadIdx.x;
    if (idx >= HID * DOUT) return;
    int k = idx / DOUT, n = idx % DOUT;
    __half* row = g_Wh + (size_t)k * NPAD;
    row[n]       = __float2half_rn(Wq[idx]);
    row[232 + n] = __float2half_rn(Wk[idx]);
    row[464 + n] = __float2half_rn(Wv[idx]);
    row[696 + n] = __float2half_rn(Ws[idx]);
}

// ---------------- fp16 HGEMM: g_qkvs = h @ Wh, CTA 128x128, K chunks of 64 ----------------
__device__ __forceinline__ void load_chunk(uint32_t as, uint32_t bs,
                                           int row0, int col0, int k0, int tid) {
#pragma unroll
    for (int j = 0; j < 4; j++) {                 // A: 1024 cp16
        int idx = tid + 256 * j;
        int m  = idx >> 3;
        int kq = (idx & 7) * 8;
        cp16(as + (m * ASTR + kq) * 2,
             g_hf16 + (size_t)(row0 + m) * HID + k0 + kq);
    }
#pragma unroll
    for (int j = 0; j < 4; j++) {                 // B: 1024 cp16
        int idx = tid + 256 * j;
        int kr = idx >> 4;
        int n  = (idx & 15) * 8;
        cp16(bs + (kr * BSTR + n) * 2,
             g_Wh + (size_t)(k0 + kr) * NPAD + col0 + n);
    }
    asm volatile("cp.async.commit_group;" ::: "memory");
}

__device__ __forceinline__ void compute_chunk(uint32_t as, uint32_t bs,
                                              int wm, int wn, int lane,
                                              float d[4][4][4]) {
    const int lrow = lane & 15;
    const int lsel = (lane >> 4) << 3;
#pragma unroll
    for (int kk = 0; kk < KC; kk += 16) {
        uint32_t af[4][4], bf[4][2];
#pragma unroll
        for (int mi = 0; mi < 4; mi++) {
            uint32_t a = as + ((wm + mi * 16 + lrow) * ASTR + kk + lsel) * 2;
            ldm4(af[mi][0], af[mi][1], af[mi][2], af[mi][3], a);
        }
#pragma unroll
        for (int nj = 0; nj < 2; nj++) {
            uint32_t a = bs + ((kk + lrow) * BSTR + wn + nj * 16 + lsel) * 2;
            uint32_t r0, r1, r2, r3;
            ldm4t(r0, r1, r2, r3, a);
            bf[nj * 2][0] = r0;     bf[nj * 2][1] = r1;
            bf[nj * 2 + 1][0] = r2; bf[nj * 2 + 1][1] = r3;
        }
#pragma unroll
        for (int mi = 0; mi < 4; mi++)
#pragma unroll
            for (int ni = 0; ni < 4; ni++)
                mma_f16(d[mi][ni][0], d[mi][ni][1], d[mi][ni][2], d[mi][ni][3],
                        af[mi][0], af[mi][1], af[mi][2], af[mi][3],
                        bf[ni][0], bf[ni][1]);
    }
}

__global__ __launch_bounds__(256) void gemm_hmma() {
    extern __shared__ __half smem[];
    const uint32_t sbase = s2u(smem);
    const uint32_t asb[2] = { sbase, sbase + (A_T + B_T) * 2 };
    const uint32_t bsb[2] = { sbase + A_T * 2, sbase + (2 * A_T + B_T) * 2 };

    const int tid  = threadIdx.x;
    const int wid  = tid >> 5;
    const int lane = tid & 31;
    const int wm = (wid & 1) * 64;
    const int wn = (wid >> 1) * 32;
    const int r  = lane >> 2;
    const int c  = lane & 3;
    const int row0 = blockIdx.y * TM;
    const int col0 = blockIdx.x * TN;

    float d[4][4][4];
#pragma unroll
    for (int mi = 0; mi < 4; mi++)
#pragma unroll
        for (int ni = 0; ni < 4; ni++)
#pragma unroll
            for (int t = 0; t < 4; t++) d[mi][ni][t] = 0.f;

    load_chunk(asb[0], bsb[0], row0, col0, 0, tid);

#pragma unroll
    for (int ch = 0; ch < NCH; ch++) {
        if (ch + 1 < NCH) {
            load_chunk(asb[(ch + 1) & 1], bsb[(ch + 1) & 1], row0, col0,
                       (ch + 1) * KC, tid);
            asm volatile("cp.async.wait_group 1;" ::: "memory");
        } else {
            asm volatile("cp.async.wait_group 0;" ::: "memory");
        }
        __syncthreads();
        compute_chunk(asb[ch & 1], bsb[ch & 1], wm, wn, lane, d);
        __syncthreads();
    }

    // epilogue: predicated stores into stride-928 qkvs
    const int c2 = c * 2;
#pragma unroll
    for (int mi = 0; mi < 4; mi++) {
#pragma unroll
        for (int ni = 0; ni < 4; ni++) {
            int row = row0 + wm + mi * 16 + r;
            int col = col0 + wn + ni * 8 + c2;
            if (col < QS) {
                *(float2*)&g_qkvs[(size_t)row * QS + col] =
                    make_float2(d[mi][ni][0], d[mi][ni][1]);
                *(float2*)&g_qkvs[(size_t)(row + 8) * QS + col] =
                    make_float2(d[mi][ni][2], d[mi][ni][3]);
            }
        }
    }
}

// ---------------- per-node edge attention (one warp per node, float4) ----------------
// Row layout: 232 floats = 58 float4; head boundary at f4 index 29 (116 floats).
// Lane owns f4 indices {lane, lane+32} (second valid for lane<26).
__global__ __launch_bounds__(256) void attn_kernel(const int* __restrict__ e32) {
    const int warp = threadIdx.x >> 5;
    const int lane = threadIdx.x & 31;
    const int node = blockIdx.x * 8 + warp;
    if (node >= N_NODES) return;
    const int is64 = g_is64;
    const bool v2 = lane < 26;          // second f4 valid
    const bool h0 = lane < 29;          // first f4 belongs to head 0
    const float4 z4 = make_float4(0.f, 0.f, 0.f, 0.f);

    const float4* row4 = (const float4*)(g_qkvs + (size_t)node * QS);
    float4 q0 = row4[lane];
    float4 q1 = v2 ? row4[lane + 32] : z4;

    int src[8];
#pragma unroll
    for (int e = 0; e < 8; e++) {
        int ei = node * 8 + e;
        src[e] = is64 ? e32[2 * ei] : e32[ei];
    }

    float s0[8], s1[8];
#pragma unroll
    for (int e = 0; e < 8; e++) {
        const float4* kp = (const float4*)(g_qkvs + (size_t)src[e] * QS + 232);
        float p0 = dot4(q0, kp[lane]);
        float p1 = v2 ? dot4(q1, kp[lane + 32]) : 0.f;
        float a0 = h0 ? p0 : 0.f;
        float a1 = h0 ? p1 : p0 + p1;
#pragma unroll
        for (int o = 16; o > 0; o >>= 1) {
            a0 += __shfl_xor_sync(0xFFFFFFFFu, a0, o);
            a1 += __shfl_xor_sync(0xFFFFFFFFu, a1, o);
        }
        s0[e] = a0; s1[e] = a1;
    }

    const float scale = rsqrtf((float)DH);
    float m0 = -1e30f, m1 = -1e30f;
#pragma unroll
    for (int e = 0; e < 8; e++) {
        s0[e] *= scale; s1[e] *= scale;
        m0 = fmaxf(m0, s0[e]); m1 = fmaxf(m1, s1[e]);
    }
    float sum0 = 0.f, sum1 = 0.f;
    float w0[8], w1[8];
#pragma unroll
    for (int e = 0; e < 8; e++) {
        w0[e] = expf(s0[e] - m0); sum0 += w0[e];
        w1[e] = expf(s1[e] - m1); sum1 += w1[e];
    }
    float inv0 = 1.f / (sum0 + 1e-16f);
    float inv1 = 1.f / (sum1 + 1e-16f);
#pragma unroll
    for (int e = 0; e < 8; e++) { w0[e] *= inv0; w1[e] *= inv1; }

    // skip init (Ws proj at float offset 696 = f4 174), then accumulate alpha*v
    float4 acc0 = row4[174 + lane];
    float4 acc1 = v2 ? row4[174 + 32 + lane] : z4;
#pragma unroll
    for (int e = 0; e < 8; e++) {
        const float4* vp = (const float4*)(g_qkvs + (size_t)src[e] * QS + 464);
        float4 v0 = vp[lane];
        float wf = h0 ? w0[e] : w1[e];
        acc0.x += wf * v0.x; acc0.y += wf * v0.y;
        acc0.z += wf * v0.z; acc0.w += wf * v0.w;
        if (v2) {
            float4 vv = vp[lane + 32];
            float ws = w1[e];
            acc1.x += ws * vv.x; acc1.y += ws * vv.y;
            acc1.z += ws * vv.z; acc1.w += ws * vv.w;
        }
    }

    float part = acc0.x + acc0.y + acc0.z + acc0.w
               + acc1.x + acc1.y + acc1.z + acc1.w;
#pragma unroll
    for (int o = 16; o > 0; o >>= 1) part += __shfl_xor_sync(0xFFFFFFFFu, part, o);

    float4* hp4 = (float4*)(g_hproj + (size_t)node * DOUT);
    hp4[lane] = acc0;
    if (v2) hp4[lane + 32] = acc1;
    if (lane == 0) g_e[node] = part * (1.f / 232.f);
}

// ---------------- per-graph softmax + weighting (warp-per-row, float4) ----------------
__global__ __launch_bounds__(128) void graph_softmax(float* __restrict__ out_alpha,
                                                     float* __restrict__ out_hw) {
    const int g = blockIdx.x;
    const int tid = threadIdx.x;
    const int wid = tid >> 5;
    const int lane = tid & 31;
    __shared__ float sh[128];
    __shared__ float salpha[NPG];
    const int base = g * NPG;

    float v = (tid < NPG) ? g_e[base + tid] : -1e30f;
    sh[tid] = v; __syncthreads();
    for (int o = 64; o > 0; o >>= 1) {
        if (tid < o) sh[tid] = fmaxf(sh[tid], sh[tid + o]);
        __syncthreads();
    }
    float m = sh[0]; __syncthreads();
    float ex = (tid < NPG) ? expf(v - m) : 0.f;
    sh[tid] = ex; __syncthreads();
    for (int o = 64; o > 0; o >>= 1) {
        if (tid < o) sh[tid] += sh[tid + o];
        __syncthreads();
    }
    float s = sh[0];
    float alpha = ex / s;
    if (tid < NPG) {
        salpha[tid] = alpha;
        out_alpha[base + tid] = alpha;
    }
    __syncthreads();

    for (int r = wid; r < NPG; r += 4) {
        float a = salpha[r];
        const float4* s4 = (const float4*)(g_hproj + (size_t)(base + r) * DOUT);
        float4* d4 = (float4*)(out_hw + (size_t)(base + r) * DOUT);
        float4 x = s4[lane];
        d4[lane] = make_float4(a * x.x, a * x.y, a * x.z, a * x.w);
        if (lane < 26) {
            float4 y = s4[lane + 32];
            d4[lane + 32] = make_float4(a * y.x, a * y.y, a * y.z, a * y.w);
        }
    }
}

// ---------------- launch ----------------
extern "C" void kernel_launch(void* const* d_in, const int* in_sizes, int n_in,
                              void* d_out, int out_size) {
    const float* h    = (const float*)d_in[0];
    const int*   edge = (const int*)  d_in[1];   // row 0 = src
    const float* Wq = (const float*)d_in[3];
    const float* Wk = (const float*)d_in[4];
    const float* Wv = (const float*)d_in[5];
    const float* Ws = (const float*)d_in[6];
    float* out = (float*)d_out;   // [0:59392) alpha_map, then h_weighted [N,232]

    cudaFuncSetAttribute(gemm_hmma, cudaFuncAttributeMaxDynamicSharedMemorySize,
                         SM_BYTES);

    detect_dtype<<<1, 32>>>(edge);
    conv_h<<<(N_NODES * HID / 4 + 255) / 256, 256>>>(h);
    pack_w<<<(HID * DOUT + 255) / 256, 256>>>(Wq, Wk, Wv, Ws);
    dim3 ggrid(NPAD / TN, N_NODES / TM);   // (8, 464)
    gemm_hmma<<<ggrid, 256, SM_BYTES>>>();
    attn_kernel<<<N_NODES / 8, 256>>>(edge);
    graph_softmax<<<NGRAPH, 128>>>(out, out + N_NODES);
}